// round 12
// baseline (speedup 1.0000x reference)
#include <cuda_runtime.h>
#include <cuda_bf16.h>
#include <math.h>
#include <stdint.h>

#define NROWS 8192
#define HID   4096
#define DIMN  4096
#define NEXP  64
#define NB    2049
#define FP    2176

#define TM 128
#define TN 256
#define TK 32
#define NK (HID / TK)
#define ROWB 80
#define A_BYTES (TM * ROWB)
#define B_BYTES (TN * ROWB)
#define STAGE (2 * A_BYTES + 2 * B_BYTES)
#define NSTAGE 3
#define GEMM_SMEM (NSTAGE * STAGE)

__device__ float  g_y  [(size_t)NROWS * HID];
__device__ float2 g_GF [(size_t)NROWS * FP];
__device__ float2 g_B  [(size_t)NROWS * FP];
__device__ float  g_attn[NROWS * NEXP];
__device__ float2 g_EF [NEXP * FP];
__device__ float2 g_LF [NEXP * FP];
__device__ float2 g_Esw[NEXP * FP];
__device__ float2 g_RF [FP];
__device__ float2 g_tw [1024];
__device__ float2 g_twr[2049];

__device__ __nv_bfloat16 g_xh[(size_t)NROWS * HID];
__device__ __nv_bfloat16 g_xl[(size_t)NROWS * HID];
__device__ __nv_bfloat16 g_wh[(size_t)DIMN * HID];
__device__ __nv_bfloat16 g_wl[(size_t)DIMN * HID];

// ----------------- helpers -----------------
__device__ __forceinline__ float2 cmulc(float2 a, float2 b) {
    return make_float2(a.x*b.x - a.y*b.y, a.x*b.y + a.y*b.x);
}
__device__ __forceinline__ uint32_t smem_u32(const void* p) {
    uint32_t a;
    asm("{ .reg .u64 t; cvta.to.shared.u64 t, %1; cvt.u32.u64 %0, t; }" : "=r"(a) : "l"(p));
    return a;
}
__device__ __forceinline__ void cp16(uint32_t dst, const void* src) {
    asm volatile("cp.async.cg.shared.global [%0], [%1], 16;" :: "r"(dst), "l"(src));
}
__device__ __forceinline__ void ldsm4(uint32_t* r, uint32_t addr) {
    asm volatile("ldmatrix.sync.aligned.m8n8.x4.shared.b16 {%0,%1,%2,%3}, [%4];"
                 : "=r"(r[0]), "=r"(r[1]), "=r"(r[2]), "=r"(r[3]) : "r"(addr));
}
__device__ __forceinline__ void mma_bf16(float* c, const uint32_t* a, const uint32_t* b) {
    asm volatile(
        "mma.sync.aligned.m16n8k16.row.col.f32.bf16.bf16.f32 "
        "{%0,%1,%2,%3}, {%4,%5,%6,%7}, {%8,%9}, {%0,%1,%2,%3};"
        : "+f"(c[0]), "+f"(c[1]), "+f"(c[2]), "+f"(c[3])
        : "r"(a[0]), "r"(a[1]), "r"(a[2]), "r"(a[3]), "r"(b[0]), "r"(b[1]));
}
__device__ __forceinline__ unsigned long long fma2u(unsigned long long a,
                                                    unsigned long long b,
                                                    unsigned long long c) {
    unsigned long long d;
    asm("fma.rn.f32x2 %0, %1, %2, %3;" : "=l"(d) : "l"(a), "l"(b), "l"(c));
    return d;
}
__device__ __forceinline__ unsigned long long rep2(float a) {
    unsigned long long d;
    asm("mov.b64 %0, {%1, %1};" : "=l"(d) : "f"(a));
    return d;
}
__device__ __forceinline__ float2 unpack2(unsigned long long u) {
    float2 f;
    asm("mov.b64 {%0, %1}, %2;" : "=f"(f.x), "=f"(f.y) : "l"(u));
    return f;
}

// ----------------- twiddle tables -----------------
__global__ void init_tables() {
    int t = blockIdx.x * 256 + threadIdx.x;
    const double PI = 3.14159265358979323846264338327950288;
    if (t < 1024) {
        double a = -2.0 * PI * (double)t / 2048.0;
        g_tw[t] = make_float2((float)cos(a), (float)sin(a));
    }
    if (t < 2049) {
        double a = -PI * (double)t / 2048.0;
        g_twr[t] = make_float2((float)cos(a), (float)sin(a));
    }
}

// ----------------- fp32 -> bf16 hi/lo split -----------------
__global__ void __launch_bounds__(256) convert_split(const float* __restrict__ src,
                                                     __nv_bfloat16* __restrict__ hi,
                                                     __nv_bfloat16* __restrict__ lo) {
    size_t idx = ((size_t)blockIdx.x * 256 + threadIdx.x) * 8;
    float4 v0 = *(const float4*)(src + idx);
    float4 v1 = *(const float4*)(src + idx + 4);
    float vs[8] = {v0.x, v0.y, v0.z, v0.w, v1.x, v1.y, v1.z, v1.w};
    uint32_t hw[4], lw[4];
#pragma unroll
    for (int j = 0; j < 4; j++) {
        __nv_bfloat16 h0 = __float2bfloat16(vs[2*j]);
        __nv_bfloat16 h1 = __float2bfloat16(vs[2*j+1]);
        __nv_bfloat16 l0 = __float2bfloat16(vs[2*j]   - __bfloat162float(h0));
        __nv_bfloat16 l1 = __float2bfloat16(vs[2*j+1] - __bfloat162float(h1));
        hw[j] = (uint32_t)__bfloat16_as_ushort(h0) | ((uint32_t)__bfloat16_as_ushort(h1) << 16);
        lw[j] = (uint32_t)__bfloat16_as_ushort(l0) | ((uint32_t)__bfloat16_as_ushort(l1) << 16);
    }
    *(uint4*)(hi + idx) = make_uint4(hw[0], hw[1], hw[2], hw[3]);
    *(uint4*)(lo + idx) = make_uint4(lw[0], lw[1], lw[2], lw[3]);
}

// ----------------- GEMM (R8-exact): bf16 3x split, 3-stage -----------------
__global__ void __launch_bounds__(512, 1) tc_gemm() {
    extern __shared__ char smem[];
    const uint32_t sb = smem_u32(smem);
    const int t = threadIdx.x;
    const int wid = t >> 5;
    const int lane = t & 31;
    const int cm = blockIdx.y * TM;
    const int cn = blockIdx.x * TN;
    const int wm = (wid & 3) * 32;
    const int wn = (wid >> 2) * 64;

    const int lr = t >> 2;
    const int lj = (t & 3) * 16;

    const uint32_t aoff = (uint32_t)(wm + (lane & 15)) * ROWB + (lane >> 4) * 16;
    const uint32_t boff = (uint32_t)(wn + ((lane >> 4) & 1) * 8 + (lane & 7)) * ROWB
                        + ((lane >> 3) & 1) * 16;

    float acc[2][8][4];
#pragma unroll
    for (int mi = 0; mi < 2; mi++)
#pragma unroll
        for (int ni = 0; ni < 8; ni++)
#pragma unroll
            for (int q = 0; q < 4; q++) acc[mi][ni][q] = 0.f;

#define PREFETCH(CH, SBUF)                                                          \
    {                                                                               \
        const size_t kb = (size_t)(CH) * TK;                                        \
        const uint32_t s0 = sb + (SBUF) * STAGE;                                    \
        cp16(s0 + lr * ROWB + lj, (const char*)(g_xh + (size_t)(cm + lr) * HID + kb) + lj); \
        cp16(s0 + A_BYTES + lr * ROWB + lj, (const char*)(g_xl + (size_t)(cm + lr) * HID + kb) + lj); \
        _Pragma("unroll")                                                           \
        for (int q = 0; q < 2; q++) {                                               \
            int n = lr + q * 128;                                                   \
            cp16(s0 + 2 * A_BYTES + n * ROWB + lj, (const char*)(g_wh + (size_t)(cn + n) * HID + kb) + lj); \
            cp16(s0 + 2 * A_BYTES + B_BYTES + n * ROWB + lj, (const char*)(g_wl + (size_t)(cn + n) * HID + kb) + lj); \
        }                                                                           \
    }

    PREFETCH(0, 0);
    asm volatile("cp.async.commit_group;");
    PREFETCH(1, 1);
    asm volatile("cp.async.commit_group;");
    asm volatile("cp.async.wait_group 1;");
    __syncthreads();

    int stage = 0;
    for (int c = 0; c < NK; c++) {
        if (c + 2 < NK) {
            int ps = stage + 2 >= NSTAGE ? stage + 2 - NSTAGE : stage + 2;
            PREFETCH(c + 2, ps);
        }
        asm volatile("cp.async.commit_group;");

        const uint32_t s0 = sb + stage * STAGE;
        const uint32_t Ah = s0 + aoff;
        const uint32_t Al = s0 + A_BYTES + aoff;
        const uint32_t Bh = s0 + 2 * A_BYTES + boff;
        const uint32_t Bl = s0 + 2 * A_BYTES + B_BYTES + boff;

#pragma unroll
        for (int kf = 0; kf < 2; kf++) {
            const uint32_t cb = kf * 32;
            uint32_t ah[2][4], al[2][4];
#pragma unroll
            for (int mi = 0; mi < 2; mi++) {
                ldsm4(ah[mi], Ah + mi * 16 * ROWB + cb);
                ldsm4(al[mi], Al + mi * 16 * ROWB + cb);
            }
#pragma unroll
            for (int np = 0; np < 4; np++) {
                uint32_t bh4[4], bl4[4];
                ldsm4(bh4, Bh + np * 16 * ROWB + cb);
                ldsm4(bl4, Bl + np * 16 * ROWB + cb);
#pragma unroll
                for (int mi = 0; mi < 2; mi++) {
                    mma_bf16(acc[mi][2 * np],     ah[mi], bh4);
                    mma_bf16(acc[mi][2 * np],     ah[mi], bl4);
                    mma_bf16(acc[mi][2 * np],     al[mi], bh4);
                    mma_bf16(acc[mi][2 * np + 1], ah[mi], bh4 + 2);
                    mma_bf16(acc[mi][2 * np + 1], ah[mi], bl4 + 2);
                    mma_bf16(acc[mi][2 * np + 1], al[mi], bh4 + 2);
                }
            }
        }

        asm volatile("cp.async.wait_group 1;");
        __syncthreads();
        stage = stage + 1 >= NSTAGE ? 0 : stage + 1;
    }

    const int qr = lane >> 2;
    const int qc = (lane & 3) * 2;
#pragma unroll
    for (int mi = 0; mi < 2; mi++) {
        int row = cm + wm + mi * 16 + qr;
        float* d0 = g_y + (size_t)row * DIMN + cn + wn;
        float* d1 = g_y + (size_t)(row + 8) * DIMN + cn + wn;
#pragma unroll
        for (int ni = 0; ni < 8; ni++) {
            *(float2*)(d0 + ni * 8 + qc) = make_float2(acc[mi][ni][0], acc[mi][ni][1]);
            *(float2*)(d1 + ni * 8 + qc) = make_float2(acc[mi][ni][2], acc[mi][ni][3]);
        }
    }
#undef PREFETCH
}

// ----------------- rfft(4096) per row (now zero-pads bins 2049..FP) -----------------
__global__ void __launch_bounds__(256) fft_rows(const float* __restrict__ src, int mode) {
    __shared__ float2 bufA[2048];
    __shared__ float2 bufB[2048];
    __shared__ float red[256];
    const int t = threadIdx.x;
    const int row = blockIdx.x;
    const float* sp = (mode == 0) ? (g_y + (size_t)row * HID) : (src + (size_t)row * HID);

    float ns = 0.f;
    for (int i = t; i < 1024; i += 256) {
        float4 v = *(const float4*)(sp + i * 4);
        ns += v.x * v.x + v.y * v.y + v.z * v.z + v.w * v.w;
        bufA[2 * i]     = make_float2(v.x, v.y);
        bufA[2 * i + 1] = make_float2(v.z, v.w);
    }
    red[t] = ns;
    __syncthreads();
    for (int s2 = 128; s2 > 0; s2 >>= 1) {
        if (t < s2) red[t] += red[t + s2];
        __syncthreads();
    }
    const float invn = 1.f / fmaxf(sqrtf(red[0]), 1e-12f);

    float2* X = bufA;
    float2* Y = bufB;
    for (int s = 0; s < 11; s++) {
        const int m = 1 << s;
        for (int i = t; i < 1024; i += 256) {
            float2 a = X[i], b = X[i + 1024];
            int jm = i & ~(m - 1);
            float2 w = g_tw[jm];
            float2 d = make_float2(a.x - b.x, a.y - b.y);
            Y[i + jm]     = make_float2(a.x + b.x, a.y + b.y);
            Y[i + jm + m] = cmulc(d, w);
        }
        float2* tmp = X; X = Y; Y = tmp;
        __syncthreads();
    }

    for (int k = t; k < FP; k += 256) {
        float2 Xk = make_float2(0.f, 0.f);
        if (k <= 2048) {
            float2 Ck = X[k & 2047];
            float2 Cm = X[(2048 - k) & 2047];
            Cm.y = -Cm.y;
            float2 tw = g_twr[k];
            float dx = Ck.x - Cm.x, dy = Ck.y - Cm.y;
            float p = tw.x * dx - tw.y * dy;
            float q = tw.x * dy + tw.y * dx;
            Xk = make_float2((0.5f * (Ck.x + Cm.x) + 0.5f * q) * invn,
                             (0.5f * (Ck.y + Cm.y) - 0.5f * p) * invn);
        }
        size_t o = (size_t)row * FP + k;
        if (mode == 0) {
            float2 r = (k <= 2048) ? g_RF[k] : make_float2(0.f, 0.f);
            float2 gf = make_float2(Xk.x * r.x + Xk.y * r.y,
                                    Xk.y * r.x - Xk.x * r.y);
            g_GF[o] = gf;
            g_B[o]  = gf;
        } else if (mode == 1) {
            g_EF[o] = Xk;
            float w = (k == 0 || k == 2048) ? 1.f : 2.f;
            g_Esw[o] = make_float2(w * Xk.x, w * Xk.y);
        } else {
            g_LF[o] = Xk;
        }
    }
}

// ----------------- RF = sum_k EF_k * LF_k -----------------
__global__ void rf_kernel() {
    int k = blockIdx.x * 256 + threadIdx.x;
    if (k > 2048) return;
    float2 acc = make_float2(0.f, 0.f);
#pragma unroll 8
    for (int j = 0; j < NEXP; j++) {
        float2 e = g_EF[(size_t)j * FP + k];
        float2 l = g_LF[(size_t)j * FP + k];
        acc.x += e.x * l.x - e.y * l.y;
        acc.y += e.x * l.y + e.y * l.x;
    }
    g_RF[k] = acc;
}

// ----------------- scores0: similarity+softmax from g_B (=GF) -----------------
__global__ void __launch_bounds__(256) scores_kernel() {
    __shared__ float2 A_s[16][33];
    __shared__ float2 E_s[16][65];
    __shared__ float  S_s[32][65];
    __shared__ float  nrm[32];
    const int t = threadIdx.x;
    const int rb = blockIdx.x * 32;
    if (t < 32) nrm[t] = 0.f;

    const int e  = t & 63;
    const int rg = t >> 6;
    const int la_row = t >> 3, la_f = (t & 7) * 2;
    const int le_e = t >> 2,  le_f = (t & 3) * 4;
    float2 acc[8];
#pragma unroll
    for (int i = 0; i < 8; i++) acc[i] = make_float2(0.f, 0.f);
    float nloc = 0.f;
    __syncthreads();

    for (int kb = 0; kb < NB; kb += 16) {
        {
            int k = kb + la_f;
            float4 v = make_float4(0.f, 0.f, 0.f, 0.f);
            if (k <= 2048) v = *(const float4*)&g_B[(size_t)(rb + la_row) * FP + k];
            A_s[la_f][la_row]     = make_float2(v.x, v.y);
            A_s[la_f + 1][la_row] = make_float2(v.z, v.w);
            float w0 = (k == 0 || k == 2048) ? 1.f : 2.f;
            nloc += w0 * (v.x * v.x + v.y * v.y) + 2.f * (v.z * v.z + v.w * v.w);
        }
        {
            int k = kb + le_f;
            float4 v0 = make_float4(0.f, 0.f, 0.f, 0.f);
            float4 v1 = make_float4(0.f, 0.f, 0.f, 0.f);
            if (k <= 2048) {
                const float4* p = (const float4*)&g_Esw[(size_t)le_e * FP + k];
                v0 = p[0]; v1 = p[1];
            }
            E_s[le_f][le_e]     = make_float2(v0.x, v0.y);
            E_s[le_f + 1][le_e] = make_float2(v0.z, v0.w);
            E_s[le_f + 2][le_e] = make_float2(v1.x, v1.y);
            E_s[le_f + 3][le_e] = make_float2(v1.z, v1.w);
        }
        __syncthreads();
#pragma unroll
        for (int f = 0; f < 16; f++) {
            float2 ev = E_s[f][e];
#pragma unroll
            for (int i = 0; i < 8; i++) {
                float2 av = A_s[f][rg * 8 + i];
                acc[i].x += av.x * ev.x;
                acc[i].y += av.y * ev.y;
            }
        }
        __syncthreads();
    }
#pragma unroll
    for (int i = 0; i < 8; i++) S_s[rg * 8 + i][e] = acc[i].x + acc[i].y;
    atomicAdd(&nrm[la_row], nloc);
    __syncthreads();

    if (t < 32) {
        int row = rb + t;
        float inv = rsqrtf(4096.f * fmaxf(nrm[t], 1e-30f));
        float mx = -1e30f;
        for (int j = 0; j < 64; j++) {
            float c = S_s[t][j] * inv;
            S_s[t][j] = c;
            mx = fmaxf(mx, c);
        }
        float sum = 0.f;
        for (int j = 0; j < 64; j++) sum += expf(10.f * (S_s[t][j] - mx));
        float isum = 1.f / sum;
        for (int j = 0; j < 64; j++)
            g_attn[row * 64 + j] = expf(10.f * (S_s[t][j] - mx)) * isum;
    }
}

// ----------------- fused iteration: attn -> (A = GF conj(attn@EF)) -> scores/attn -----------------
// grid = NROWS/16, 256 threads. final_mode: emit weights/indices/scores instead of attn.
__global__ void __launch_bounds__(256) fused_iter(int final_mode, float* out,
                                                  int woff, int ioff, int soff) {
    __shared__ float  attn_s[16][65];
    __shared__ float2 E_s[16][65];    // [f][j]
    __shared__ float2 A_s[16][17];    // [r][f], w-scaled
    __shared__ float  S_s[16][64];
    __shared__ float  nrm_s[16];
    const int t = threadIdx.x;
    const int rb = blockIdx.x * 16;

    for (int idx = t; idx < 16 * 64; idx += 256)
        attn_s[idx >> 6][idx & 63] = g_attn[(rb + (idx >> 6)) * 64 + (idx & 63)];
    if (t < 16) nrm_s[t] = 0.f;

    const int r  = t >> 4;        // 0..15
    const int fi = t & 15;        // 0..15
    const int lj = t >> 2;        // 0..63 (E loader j)
    const int lf = (t & 3) * 4;   // E loader f base
    float nloc = 0.f;
    unsigned long long acc2[4];
#pragma unroll
    for (int q = 0; q < 4; q++) acc2[q] = 0ULL;
    __syncthreads();

    for (int kb = 0; kb < 2064; kb += 16) {
        // load E chunk [f][j] (transposed from g_EF[j][f]); padding bins are zero
        {
            const float4* p = (const float4*)&g_EF[(size_t)lj * FP + kb + lf];
            float4 v0 = p[0], v1 = p[1];
            E_s[lf    ][lj] = make_float2(v0.x, v0.y);
            E_s[lf + 1][lj] = make_float2(v0.z, v0.w);
            E_s[lf + 2][lj] = make_float2(v1.x, v1.y);
            E_s[lf + 3][lj] = make_float2(v1.z, v1.w);
        }
        __syncthreads();
        // phase 1: zc, A, norm
        {
            unsigned long long zc = 0ULL;
#pragma unroll 8
            for (int j = 0; j < 64; j++)
                zc = fma2u(rep2(attn_s[r][j]),
                           *(const unsigned long long*)&E_s[fi][j], zc);
            float2 z = unpack2(zc);
            int k = kb + fi;
            float2 gf = g_GF[(size_t)(rb + r) * FP + k];
            float2 a = make_float2(gf.x * z.x + gf.y * z.y,
                                   gf.y * z.x - gf.x * z.y);   // GF * conj(zc)
            float w = (k == 0 || k == 2048) ? 1.f : 2.f;
            nloc += w * (a.x * a.x + a.y * a.y);
            A_s[r][fi] = make_float2(w * a.x, w * a.y);
        }
        __syncthreads();
        // phase 2: score partials, j = fi + 16q
#pragma unroll
        for (int f = 0; f < 16; f++) {
            unsigned long long av = *(const unsigned long long*)&A_s[r][f];
#pragma unroll
            for (int q = 0; q < 4; q++)
                acc2[q] = fma2u(av,
                                *(const unsigned long long*)&E_s[f][fi + 16 * q],
                                acc2[q]);
        }
        __syncthreads();
    }

#pragma unroll
    for (int q = 0; q < 4; q++) {
        float2 p = unpack2(acc2[q]);
        S_s[r][fi + 16 * q] = p.x + p.y;
    }
    atomicAdd(&nrm_s[r], nloc);
    __syncthreads();

    if (t < 16) {
        int row = rb + t;
        float inv = rsqrtf(4096.f * fmaxf(nrm_s[t], 1e-30f));
        float mx = -1e30f;
        for (int j = 0; j < 64; j++) {
            float c = S_s[t][j] * inv;
            S_s[t][j] = c;
            mx = fmaxf(mx, c);
        }
        if (!final_mode) {
            float sum = 0.f;
            for (int j = 0; j < 64; j++) sum += expf(10.f * (S_s[t][j] - mx));
            float isum = 1.f / sum;
            for (int j = 0; j < 64; j++)
                g_attn[row * 64 + j] = expf(10.f * (S_s[t][j] - mx)) * isum;
        } else {
            float s1 = -1e30f, s2 = -1e30f;
            int i1 = 0, i2 = 0;
            for (int j = 0; j < 64; j++) {
                float c = S_s[t][j];
                if (c > s1)      { s2 = s1; i2 = i1; s1 = c; i1 = j; }
                else if (c > s2) { s2 = c; i2 = j; }
            }
            float w1 = 1.f / (1.f + expf(s2 - s1));
            if (woff >= 0) { out[woff + row * 2] = w1; out[woff + row * 2 + 1] = 1.f - w1; }
            if (ioff >= 0) { out[ioff + row * 2] = (float)i1; out[ioff + row * 2 + 1] = (float)i2; }
        }
    }
    if (final_mode) {
        __syncthreads();
        for (int idx = t; idx < 16 * 64; idx += 256)
            out[soff + (rb + (idx >> 6)) * 64 + (idx & 63)] = S_s[idx >> 6][idx & 63];
    }
}

// ----------------- launch -----------------
extern "C" void kernel_launch(void* const* d_in, const int* in_sizes, int n_in,
                              void* d_out, int out_size) {
    const float* x      = (const float*)d_in[0];
    const float* W      = (const float*)d_in[1];
    const float* labels = (const float*)d_in[2];
    const float* sigs   = (const float*)d_in[3];
    float* out = (float*)d_out;

    cudaFuncSetAttribute(tc_gemm, cudaFuncAttributeMaxDynamicSharedMemorySize, GEMM_SMEM);

    init_tables<<<9, 256>>>();

    __nv_bfloat16 *xh, *xl, *wh, *wl;
    cudaGetSymbolAddress((void**)&xh, g_xh);
    cudaGetSymbolAddress((void**)&xl, g_xl);
    cudaGetSymbolAddress((void**)&wh, g_wh);
    cudaGetSymbolAddress((void**)&wl, g_wl);
    convert_split<<<(NROWS * HID) / (256 * 8), 256>>>(x, xh, xl);
    convert_split<<<(DIMN * HID) / (256 * 8), 256>>>(W, wh, wl);

    tc_gemm<<<dim3(DIMN / TN, NROWS / TM), 512, GEMM_SMEM>>>();

    fft_rows<<<NEXP, 256>>>(sigs, 1);
    fft_rows<<<NEXP, 256>>>(labels, 2);
    rf_kernel<<<9, 256>>>();
    fft_rows<<<NROWS, 256>>>(x, 0);

    scores_kernel<<<NROWS / 32, 256>>>();          // attn from z0 = GF
    fused_iter<<<NROWS / 16, 256>>>(0, nullptr, -1, -1, -1);
    fused_iter<<<NROWS / 16, 256>>>(0, nullptr, -1, -1, -1);

    int woff = -1, ioff = -1, soff = 0;
    if (out_size >= NROWS * 68) { woff = 0; ioff = NROWS * 2; soff = NROWS * 4; }
    fused_iter<<<NROWS / 16, 256>>>(1, out, woff, ioff, soff);
}

// round 14
// speedup vs baseline: 1.2385x; 1.2385x over previous
#include <cuda_runtime.h>
#include <cuda_bf16.h>
#include <math.h>
#include <stdint.h>

#define NROWS 8192
#define HID   4096
#define DIMN  4096
#define NEXP  64
#define NB    2049
#define FP    2176

// GEMM: 128x256 CTA, 512 threads, TK=64, 2-stage pipeline
#define TM 128
#define TN 256
#define TK 64
#define NK (HID / TK)          // 64 iterations
#define ROWB 144               // 128B data + 16B pad (36 words: conflict-free)
#define A_BYTES (TM * ROWB)    // 18432
#define B_BYTES (TN * ROWB)    // 36864
#define STAGE (2 * A_BYTES + 2 * B_BYTES)   // 110592
#define GEMM_SMEM (2 * STAGE)               // 221184

__device__ float  g_y  [(size_t)NROWS * HID];
__device__ float2 g_GF [(size_t)NROWS * FP];
__device__ float2 g_B  [(size_t)NROWS * FP];
__device__ float  g_attn[NROWS * NEXP];
__device__ float2 g_EF [NEXP * FP];
__device__ float2 g_LF [NEXP * FP];
__device__ float2 g_Esw[NEXP * FP];
__device__ float2 g_RF [FP];
__device__ float2 g_tw [1024];
__device__ float2 g_twr[2049];

__device__ __nv_bfloat16 g_xh[(size_t)NROWS * HID];
__device__ __nv_bfloat16 g_xl[(size_t)NROWS * HID];
__device__ __nv_bfloat16 g_wh[(size_t)DIMN * HID];
__device__ __nv_bfloat16 g_wl[(size_t)DIMN * HID];

// ----------------- helpers -----------------
__device__ __forceinline__ float2 cmulc(float2 a, float2 b) {
    return make_float2(a.x*b.x - a.y*b.y, a.x*b.y + a.y*b.x);
}
__device__ __forceinline__ uint32_t smem_u32(const void* p) {
    uint32_t a;
    asm("{ .reg .u64 t; cvta.to.shared.u64 t, %1; cvt.u32.u64 %0, t; }" : "=r"(a) : "l"(p));
    return a;
}
__device__ __forceinline__ void cp16(uint32_t dst, const void* src) {
    asm volatile("cp.async.cg.shared.global [%0], [%1], 16;" :: "r"(dst), "l"(src));
}
__device__ __forceinline__ void ldsm4(uint32_t* r, uint32_t addr) {
    asm volatile("ldmatrix.sync.aligned.m8n8.x4.shared.b16 {%0,%1,%2,%3}, [%4];"
                 : "=r"(r[0]), "=r"(r[1]), "=r"(r[2]), "=r"(r[3]) : "r"(addr));
}
__device__ __forceinline__ void mma_bf16(float* c, const uint32_t* a, const uint32_t* b) {
    asm volatile(
        "mma.sync.aligned.m16n8k16.row.col.f32.bf16.bf16.f32 "
        "{%0,%1,%2,%3}, {%4,%5,%6,%7}, {%8,%9}, {%0,%1,%2,%3};"
        : "+f"(c[0]), "+f"(c[1]), "+f"(c[2]), "+f"(c[3])
        : "r"(a[0]), "r"(a[1]), "r"(a[2]), "r"(a[3]), "r"(b[0]), "r"(b[1]));
}

// ----------------- twiddle tables -----------------
__global__ void init_tables() {
    int t = blockIdx.x * 256 + threadIdx.x;
    const double PI = 3.14159265358979323846264338327950288;
    if (t < 1024) {
        double a = -2.0 * PI * (double)t / 2048.0;
        g_tw[t] = make_float2((float)cos(a), (float)sin(a));
    }
    if (t < 2049) {
        double a = -PI * (double)t / 2048.0;
        g_twr[t] = make_float2((float)cos(a), (float)sin(a));
    }
}

// ----------------- fp32 -> bf16 hi/lo split -----------------
__global__ void __launch_bounds__(256) convert_split(const float* __restrict__ src,
                                                     __nv_bfloat16* __restrict__ hi,
                                                     __nv_bfloat16* __restrict__ lo) {
    size_t idx = ((size_t)blockIdx.x * 256 + threadIdx.x) * 8;
    float4 v0 = *(const float4*)(src + idx);
    float4 v1 = *(const float4*)(src + idx + 4);
    float vs[8] = {v0.x, v0.y, v0.z, v0.w, v1.x, v1.y, v1.z, v1.w};
    uint32_t hw[4], lw[4];
#pragma unroll
    for (int j = 0; j < 4; j++) {
        __nv_bfloat16 h0 = __float2bfloat16(vs[2*j]);
        __nv_bfloat16 h1 = __float2bfloat16(vs[2*j+1]);
        __nv_bfloat16 l0 = __float2bfloat16(vs[2*j]   - __bfloat162float(h0));
        __nv_bfloat16 l1 = __float2bfloat16(vs[2*j+1] - __bfloat162float(h1));
        hw[j] = (uint32_t)__bfloat16_as_ushort(h0) | ((uint32_t)__bfloat16_as_ushort(h1) << 16);
        lw[j] = (uint32_t)__bfloat16_as_ushort(l0) | ((uint32_t)__bfloat16_as_ushort(l1) << 16);
    }
    *(uint4*)(hi + idx) = make_uint4(hw[0], hw[1], hw[2], hw[3]);
    *(uint4*)(lo + idx) = make_uint4(lw[0], lw[1], lw[2], lw[3]);
}

// ----------------- GEMM: bf16 3x split, TK=64, 2-stage, 1 barrier/iter -----------------
__global__ void __launch_bounds__(512, 1) tc_gemm() {
    extern __shared__ char smem[];
    const uint32_t sb = smem_u32(smem);
    const int t = threadIdx.x;
    const int wid = t >> 5;
    const int lane = t & 31;
    const int cm = blockIdx.y * TM;
    const int cn = blockIdx.x * TN;
    const int wm = (wid & 3) * 32;
    const int wn = (wid >> 2) * 64;

    const int lr = t >> 2;              // 0..127
    const int lj = (t & 3) * 16;        // 0/16/32/48; second half via +64

    const uint32_t aoff = (uint32_t)(wm + (lane & 15)) * ROWB + (lane >> 4) * 16;
    const uint32_t boff = (uint32_t)(wn + ((lane >> 4) & 1) * 8 + (lane & 7)) * ROWB
                        + ((lane >> 3) & 1) * 16;

    float acc[2][8][4];
#pragma unroll
    for (int mi = 0; mi < 2; mi++)
#pragma unroll
        for (int ni = 0; ni < 8; ni++)
#pragma unroll
            for (int q = 0; q < 4; q++) acc[mi][ni][q] = 0.f;

#define PREFETCH(CH, SBUF)                                                            \
    {                                                                                 \
        const size_t kb = (size_t)(CH) * TK;                                          \
        const uint32_t s0 = sb + (SBUF) * STAGE;                                      \
        const char* axh = (const char*)(g_xh + (size_t)(cm + lr) * HID + kb);         \
        const char* axl = (const char*)(g_xl + (size_t)(cm + lr) * HID + kb);         \
        uint32_t da = s0 + lr * ROWB;                                                 \
        cp16(da + lj, axh + lj);            cp16(da + lj + 64, axh + lj + 64);        \
        cp16(da + A_BYTES + lj, axl + lj);  cp16(da + A_BYTES + lj + 64, axl + lj + 64); \
        _Pragma("unroll")                                                             \
        for (int q = 0; q < 2; q++) {                                                 \
            int n = lr + q * 128;                                                     \
            const char* bwh = (const char*)(g_wh + (size_t)(cn + n) * HID + kb);      \
            const char* bwl = (const char*)(g_wl + (size_t)(cn + n) * HID + kb);      \
            uint32_t db = s0 + 2 * A_BYTES + n * ROWB;                                \
            cp16(db + lj, bwh + lj);            cp16(db + lj + 64, bwh + lj + 64);    \
            cp16(db + B_BYTES + lj, bwl + lj);  cp16(db + B_BYTES + lj + 64, bwl + lj + 64); \
        }                                                                             \
    }

    // prologue: chunk 0 into stage 0
    PREFETCH(0, 0);
    asm volatile("cp.async.commit_group;");
    asm volatile("cp.async.wait_group 0;");
    __syncthreads();

    for (int c = 0; c < NK; c++) {
        const int s = c & 1;
        // overlap: load chunk c+1 into the other stage while computing on s
        if (c + 1 < NK) PREFETCH(c + 1, s ^ 1);
        asm volatile("cp.async.commit_group;");

        const uint32_t s0 = sb + s * STAGE;
        const uint32_t Ah = s0 + aoff;
        const uint32_t Al = s0 + A_BYTES + aoff;
        const uint32_t Bh = s0 + 2 * A_BYTES + boff;
        const uint32_t Bl = s0 + 2 * A_BYTES + B_BYTES + boff;

#pragma unroll
        for (int kf = 0; kf < 4; kf++) {
            const uint32_t cb = kf * 32;
            uint32_t ah[2][4], al[2][4];
#pragma unroll
            for (int mi = 0; mi < 2; mi++) {
                ldsm4(ah[mi], Ah + mi * 16 * ROWB + cb);
                ldsm4(al[mi], Al + mi * 16 * ROWB + cb);
            }
#pragma unroll
            for (int np = 0; np < 4; np++) {
                uint32_t bh4[4], bl4[4];
                ldsm4(bh4, Bh + np * 16 * ROWB + cb);
                ldsm4(bl4, Bl + np * 16 * ROWB + cb);
#pragma unroll
                for (int mi = 0; mi < 2; mi++) {
                    mma_bf16(acc[mi][2 * np],     ah[mi], bh4);
                    mma_bf16(acc[mi][2 * np],     ah[mi], bl4);
                    mma_bf16(acc[mi][2 * np],     al[mi], bh4);
                    mma_bf16(acc[mi][2 * np + 1], ah[mi], bh4 + 2);
                    mma_bf16(acc[mi][2 * np + 1], ah[mi], bl4 + 2);
                    mma_bf16(acc[mi][2 * np + 1], al[mi], bh4 + 2);
                }
            }
        }

        asm volatile("cp.async.wait_group 0;");
        __syncthreads();
    }

    const int qr = lane >> 2;
    const int qc = (lane & 3) * 2;
#pragma unroll
    for (int mi = 0; mi < 2; mi++) {
        int row = cm + wm + mi * 16 + qr;
        float* d0 = g_y + (size_t)row * DIMN + cn + wn;
        float* d1 = g_y + (size_t)(row + 8) * DIMN + cn + wn;
#pragma unroll
        for (int ni = 0; ni < 8; ni++) {
            *(float2*)(d0 + ni * 8 + qc) = make_float2(acc[mi][ni][0], acc[mi][ni][1]);
            *(float2*)(d1 + ni * 8 + qc) = make_float2(acc[mi][ni][2], acc[mi][ni][3]);
        }
    }
#undef PREFETCH
}

// ----------------- rfft(4096) per row -----------------
// mode 0: g_y rows -> g_GF only (first scores call reads GF directly)
__global__ void __launch_bounds__(256) fft_rows(const float* __restrict__ src, int mode) {
    __shared__ float2 bufA[2048];
    __shared__ float2 bufB[2048];
    __shared__ float red[256];
    const int t = threadIdx.x;
    const int row = blockIdx.x;
    const float* sp = (mode == 0) ? (g_y + (size_t)row * HID) : (src + (size_t)row * HID);

    float ns = 0.f;
    for (int i = t; i < 1024; i += 256) {
        float4 v = *(const float4*)(sp + i * 4);
        ns += v.x * v.x + v.y * v.y + v.z * v.z + v.w * v.w;
        bufA[2 * i]     = make_float2(v.x, v.y);
        bufA[2 * i + 1] = make_float2(v.z, v.w);
    }
    red[t] = ns;
    __syncthreads();
    for (int s2 = 128; s2 > 0; s2 >>= 1) {
        if (t < s2) red[t] += red[t + s2];
        __syncthreads();
    }
    const float invn = 1.f / fmaxf(sqrtf(red[0]), 1e-12f);

    float2* X = bufA;
    float2* Y = bufB;
    for (int s = 0; s < 11; s++) {
        const int m = 1 << s;
        for (int i = t; i < 1024; i += 256) {
            float2 a = X[i], b = X[i + 1024];
            int jm = i & ~(m - 1);
            float2 w = g_tw[jm];
            float2 d = make_float2(a.x - b.x, a.y - b.y);
            Y[i + jm]     = make_float2(a.x + b.x, a.y + b.y);
            Y[i + jm + m] = cmulc(d, w);
        }
        float2* tmp = X; X = Y; Y = tmp;
        __syncthreads();
    }

    for (int k = t; k <= 2048; k += 256) {
        float2 Ck = X[k & 2047];
        float2 Cm = X[(2048 - k) & 2047];
        Cm.y = -Cm.y;
        float2 tw = g_twr[k];
        float dx = Ck.x - Cm.x, dy = Ck.y - Cm.y;
        float p = tw.x * dx - tw.y * dy;
        float q = tw.x * dy + tw.y * dx;
        float2 Xk = make_float2((0.5f * (Ck.x + Cm.x) + 0.5f * q) * invn,
                                (0.5f * (Ck.y + Cm.y) - 0.5f * p) * invn);
        size_t o = (size_t)row * FP + k;
        if (mode == 0) {
            float2 r = g_RF[k];
            g_GF[o] = make_float2(Xk.x * r.x + Xk.y * r.y,
                                  Xk.y * r.x - Xk.x * r.y);
        } else if (mode == 1) {
            g_EF[o] = Xk;
            float w = (k == 0 || k == 2048) ? 1.f : 2.f;
            g_Esw[o] = make_float2(w * Xk.x, w * Xk.y);
        } else {
            g_LF[o] = Xk;
        }
    }
}

// ----------------- RF = sum_k EF_k * LF_k -----------------
__global__ void rf_kernel() {
    int k = blockIdx.x * 256 + threadIdx.x;
    if (k > 2048) return;
    float2 acc = make_float2(0.f, 0.f);
#pragma unroll 8
    for (int j = 0; j < NEXP; j++) {
        float2 e = g_EF[(size_t)j * FP + k];
        float2 l = g_LF[(size_t)j * FP + k];
        acc.x += e.x * l.x - e.y * l.y;
        acc.y += e.x * l.y + e.y * l.x;
    }
    g_RF[k] = acc;
}

// ----------------- similarity + softmax (iter) / outputs (final) -----------------
__global__ void __launch_bounds__(256) scores_kernel(const float2* __restrict__ Bsrc,
                                                     int final_mode, float* out,
                                                     int woff, int ioff, int soff) {
    __shared__ float2 A_s[16][33];
    __shared__ float2 E_s[16][65];
    __shared__ float  S_s[32][65];
    __shared__ float  nrm[32];
    const int t = threadIdx.x;
    const int rb = blockIdx.x * 32;
    if (t < 32) nrm[t] = 0.f;

    const int e  = t & 63;
    const int rg = t >> 6;
    const int la_row = t >> 3, la_f = (t & 7) * 2;
    const int le_e = t >> 2,  le_f = (t & 3) * 4;
    float2 acc[8];
#pragma unroll
    for (int i = 0; i < 8; i++) acc[i] = make_float2(0.f, 0.f);
    float nloc = 0.f;
    __syncthreads();

    for (int kb = 0; kb < NB; kb += 16) {
        {
            int k = kb + la_f;
            float4 v = make_float4(0.f, 0.f, 0.f, 0.f);
            if (k <= 2048) v = *(const float4*)&Bsrc[(size_t)(rb + la_row) * FP + k];
            A_s[la_f][la_row]     = make_float2(v.x, v.y);
            A_s[la_f + 1][la_row] = make_float2(v.z, v.w);
            float w0 = (k == 0 || k == 2048) ? 1.f : 2.f;
            nloc += w0 * (v.x * v.x + v.y * v.y) + 2.f * (v.z * v.z + v.w * v.w);
        }
        {
            int k = kb + le_f;
            float4 v0 = make_float4(0.f, 0.f, 0.f, 0.f);
            float4 v1 = make_float4(0.f, 0.f, 0.f, 0.f);
            if (k <= 2048) {
                const float4* p = (const float4*)&g_Esw[(size_t)le_e * FP + k];
                v0 = p[0]; v1 = p[1];
            }
            E_s[le_f][le_e]     = make_float2(v0.x, v0.y);
            E_s[le_f + 1][le_e] = make_float2(v0.z, v0.w);
            E_s[le_f + 2][le_e] = make_float2(v1.x, v1.y);
            E_s[le_f + 3][le_e] = make_float2(v1.z, v1.w);
        }
        __syncthreads();
#pragma unroll
        for (int f = 0; f < 16; f++) {
            float2 ev = E_s[f][e];
#pragma unroll
            for (int i = 0; i < 8; i++) {
                float2 av = A_s[f][rg * 8 + i];
                acc[i].x += av.x * ev.x;
                acc[i].y += av.y * ev.y;
            }
        }
        __syncthreads();
    }
#pragma unroll
    for (int i = 0; i < 8; i++) S_s[rg * 8 + i][e] = acc[i].x + acc[i].y;
    atomicAdd(&nrm[la_row], nloc);
    __syncthreads();

    if (t < 32) {
        int row = rb + t;
        float inv = rsqrtf(4096.f * fmaxf(nrm[t], 1e-30f));
        float mx = -1e30f;
        for (int j = 0; j < 64; j++) {
            float c = S_s[t][j] * inv;
            S_s[t][j] = c;
            mx = fmaxf(mx, c);
        }
        if (!final_mode) {
            float sum = 0.f;
            for (int j = 0; j < 64; j++) sum += expf(10.f * (S_s[t][j] - mx));
            float isum = 1.f / sum;
            for (int j = 0; j < 64; j++)
                g_attn[row * 64 + j] = expf(10.f * (S_s[t][j] - mx)) * isum;
        } else {
            float s1 = -1e30f, s2 = -1e30f;
            int i1 = 0, i2 = 0;
            for (int j = 0; j < 64; j++) {
                float c = S_s[t][j];
                if (c > s1)      { s2 = s1; i2 = i1; s1 = c; i1 = j; }
                else if (c > s2) { s2 = c; i2 = j; }
            }
            float w1 = 1.f / (1.f + expf(s2 - s1));
            if (woff >= 0) { out[woff + row * 2] = w1; out[woff + row * 2 + 1] = 1.f - w1; }
            if (ioff >= 0) { out[ioff + row * 2] = (float)i1; out[ioff + row * 2 + 1] = (float)i2; }
        }
    }
    if (final_mode) {
        __syncthreads();
        for (int idx = t; idx < 32 * 64; idx += 256)
            out[soff + (rb + (idx >> 6)) * 64 + (idx & 63)] = S_s[idx >> 6][idx & 63];
    }
}

// ----------------- A_next = GF * conj(attn @ EF) -----------------
__global__ void __launch_bounds__(256) update_kernel() {
    __shared__ float attn_s[16][65];
    const int t = threadIdx.x;
    const int rb = blockIdx.y * 16;
    const int kb = blockIdx.x * 128;
    for (int idx = t; idx < 16 * 64; idx += 256)
        attn_s[idx >> 6][idx & 63] = g_attn[(rb + (idx >> 6)) * 64 + (idx & 63)];
    __syncthreads();

    const int r  = t >> 4;
    const int fo = (t & 15) * 2;
    float2 acc[8];
#pragma unroll
    for (int m = 0; m < 8; m++) acc[m] = make_float2(0.f, 0.f);
#pragma unroll 4
    for (int j = 0; j < 64; j++) {
        float a = attn_s[r][j];
        const float4* ep = (const float4*)&g_EF[(size_t)j * FP + kb + fo];
#pragma unroll
        for (int m = 0; m < 4; m++) {
            float4 e = ep[m * 16];
            acc[2 * m].x     += a * e.x; acc[2 * m].y     += a * e.y;
            acc[2 * m + 1].x += a * e.z; acc[2 * m + 1].y += a * e.w;
        }
    }
    const size_t base = (size_t)(rb + r) * FP + kb + fo;
#pragma unroll
    for (int m = 0; m < 4; m++) {
        const float4 g4 = *(const float4*)&g_GF[base + m * 32];
        float2 z0 = acc[2 * m], z1 = acc[2 * m + 1];
        float4 o;
        o.x = g4.x * z0.x + g4.y * z0.y;
        o.y = g4.y * z0.x - g4.x * z0.y;
        o.z = g4.z * z1.x + g4.w * z1.y;
        o.w = g4.w * z1.x - g4.z * z1.y;
        *(float4*)&g_B[base + m * 32] = o;
    }
}

// ----------------- launch -----------------
extern "C" void kernel_launch(void* const* d_in, const int* in_sizes, int n_in,
                              void* d_out, int out_size) {
    const float* x      = (const float*)d_in[0];
    const float* W      = (const float*)d_in[1];
    const float* labels = (const float*)d_in[2];
    const float* sigs   = (const float*)d_in[3];
    float* out = (float*)d_out;

    cudaFuncSetAttribute(tc_gemm, cudaFuncAttributeMaxDynamicSharedMemorySize, GEMM_SMEM);

    init_tables<<<9, 256>>>();

    __nv_bfloat16 *xh, *xl, *wh, *wl;
    float2 *gfp, *bp;
    cudaGetSymbolAddress((void**)&xh, g_xh);
    cudaGetSymbolAddress((void**)&xl, g_xl);
    cudaGetSymbolAddress((void**)&wh, g_wh);
    cudaGetSymbolAddress((void**)&wl, g_wl);
    cudaGetSymbolAddress((void**)&gfp, g_GF);
    cudaGetSymbolAddress((void**)&bp, g_B);
    convert_split<<<(NROWS * HID) / (256 * 8), 256>>>(x, xh, xl);
    convert_split<<<(DIMN * HID) / (256 * 8), 256>>>(W, wh, wl);

    tc_gemm<<<dim3(DIMN / TN, NROWS / TM), 512, GEMM_SMEM>>>();

    fft_rows<<<NEXP, 256>>>(sigs, 1);
    fft_rows<<<NEXP, 256>>>(labels, 2);
    rf_kernel<<<9, 256>>>();
    fft_rows<<<NROWS, 256>>>(x, 0);

    // iteration 1 reads GF directly (no g_B copy needed)
    scores_kernel<<<NROWS / 32, 256>>>(gfp, 0, nullptr, -1, -1, -1);
    update_kernel<<<dim3(17, NROWS / 16), 256>>>();
    for (int it = 1; it < 3; it++) {
        scores_kernel<<<NROWS / 32, 256>>>(bp, 0, nullptr, -1, -1, -1);
        update_kernel<<<dim3(17, NROWS / 16), 256>>>();
    }

    int woff = -1, ioff = -1, soff = 0;
    if (out_size >= NROWS * 68) { woff = 0; ioff = NROWS * 2; soff = NROWS * 4; }
    scores_kernel<<<NROWS / 32, 256>>>(bp, 1, out, woff, ioff, soff);
}

// round 15
// speedup vs baseline: 1.2552x; 1.0135x over previous
#include <cuda_runtime.h>
#include <cuda_bf16.h>
#include <math.h>
#include <stdint.h>

#define NROWS 8192
#define HID   4096
#define DIMN  4096
#define NEXP  64
#define NB    2049
#define FP    2176

// GEMM: 128x256 CTA, 512 threads, TK=64, 2-stage pipeline
#define TM 128
#define TN 256
#define TK 64
#define NK (HID / TK)          // 64 iterations
#define ROWB 144               // 128B data + 16B pad (36 words: conflict-free)
#define A_BYTES (TM * ROWB)    // 18432
#define B_BYTES (TN * ROWB)    // 36864
#define STAGE (2 * A_BYTES + 2 * B_BYTES)   // 110592
#define GEMM_SMEM (2 * STAGE)               // 221184

__device__ float  g_y  [(size_t)NROWS * HID];
__device__ float2 g_GF [(size_t)NROWS * FP];
__device__ float2 g_B  [(size_t)NROWS * FP];
__device__ float  g_attn[NROWS * NEXP];
__device__ float2 g_EF [NEXP * FP];
__device__ float2 g_LF [NEXP * FP];
__device__ float2 g_Esw[NEXP * FP];
__device__ float2 g_RF [FP];
__device__ float2 g_tw [1024];
__device__ float2 g_twr[2049];

__device__ __nv_bfloat16 g_xh[(size_t)NROWS * HID];
__device__ __nv_bfloat16 g_xl[(size_t)NROWS * HID];
__device__ __nv_bfloat16 g_wh[(size_t)DIMN * HID];
__device__ __nv_bfloat16 g_wl[(size_t)DIMN * HID];

// ----------------- helpers -----------------
__device__ __forceinline__ float2 cmulc(float2 a, float2 b) {
    return make_float2(a.x*b.x - a.y*b.y, a.x*b.y + a.y*b.x);
}
__device__ __forceinline__ uint32_t smem_u32(const void* p) {
    uint32_t a;
    asm("{ .reg .u64 t; cvta.to.shared.u64 t, %1; cvt.u32.u64 %0, t; }" : "=r"(a) : "l"(p));
    return a;
}
__device__ __forceinline__ void cp16(uint32_t dst, const void* src) {
    asm volatile("cp.async.cg.shared.global [%0], [%1], 16;" :: "r"(dst), "l"(src));
}
__device__ __forceinline__ void ldsm4(uint32_t* r, uint32_t addr) {
    asm volatile("ldmatrix.sync.aligned.m8n8.x4.shared.b16 {%0,%1,%2,%3}, [%4];"
                 : "=r"(r[0]), "=r"(r[1]), "=r"(r[2]), "=r"(r[3]) : "r"(addr));
}
__device__ __forceinline__ void mma_bf16(float* c, const uint32_t* a, const uint32_t* b) {
    asm volatile(
        "mma.sync.aligned.m16n8k16.row.col.f32.bf16.bf16.f32 "
        "{%0,%1,%2,%3}, {%4,%5,%6,%7}, {%8,%9}, {%0,%1,%2,%3};"
        : "+f"(c[0]), "+f"(c[1]), "+f"(c[2]), "+f"(c[3])
        : "r"(a[0]), "r"(a[1]), "r"(a[2]), "r"(a[3]), "r"(b[0]), "r"(b[1]));
}

// ----------------- twiddle tables -----------------
__global__ void init_tables() {
    int t = blockIdx.x * 256 + threadIdx.x;
    const double PI = 3.14159265358979323846264338327950288;
    if (t < 1024) {
        double a = -2.0 * PI * (double)t / 2048.0;
        g_tw[t] = make_float2((float)cos(a), (float)sin(a));
    }
    if (t < 2049) {
        double a = -PI * (double)t / 2048.0;
        g_twr[t] = make_float2((float)cos(a), (float)sin(a));
    }
}

// ----------------- fp32 -> bf16 hi/lo split -----------------
__global__ void __launch_bounds__(256) convert_split(const float* __restrict__ src,
                                                     __nv_bfloat16* __restrict__ hi,
                                                     __nv_bfloat16* __restrict__ lo) {
    size_t idx = ((size_t)blockIdx.x * 256 + threadIdx.x) * 8;
    float4 v0 = *(const float4*)(src + idx);
    float4 v1 = *(const float4*)(src + idx + 4);
    float vs[8] = {v0.x, v0.y, v0.z, v0.w, v1.x, v1.y, v1.z, v1.w};
    uint32_t hw[4], lw[4];
#pragma unroll
    for (int j = 0; j < 4; j++) {
        __nv_bfloat16 h0 = __float2bfloat16(vs[2*j]);
        __nv_bfloat16 h1 = __float2bfloat16(vs[2*j+1]);
        __nv_bfloat16 l0 = __float2bfloat16(vs[2*j]   - __bfloat162float(h0));
        __nv_bfloat16 l1 = __float2bfloat16(vs[2*j+1] - __bfloat162float(h1));
        hw[j] = (uint32_t)__bfloat16_as_ushort(h0) | ((uint32_t)__bfloat16_as_ushort(h1) << 16);
        lw[j] = (uint32_t)__bfloat16_as_ushort(l0) | ((uint32_t)__bfloat16_as_ushort(l1) << 16);
    }
    *(uint4*)(hi + idx) = make_uint4(hw[0], hw[1], hw[2], hw[3]);
    *(uint4*)(lo + idx) = make_uint4(lw[0], lw[1], lw[2], lw[3]);
}

// ----------------- GEMM: bf16 3x split, TK=64, 2-stage, 1 barrier/iter -----------------
__global__ void __launch_bounds__(512, 1) tc_gemm() {
    extern __shared__ char smem[];
    const uint32_t sb = smem_u32(smem);
    const int t = threadIdx.x;
    const int wid = t >> 5;
    const int lane = t & 31;
    const int cm = blockIdx.y * TM;
    const int cn = blockIdx.x * TN;
    const int wm = (wid & 3) * 32;
    const int wn = (wid >> 2) * 64;

    const int lr = t >> 2;
    const int lj = (t & 3) * 16;

    const uint32_t aoff = (uint32_t)(wm + (lane & 15)) * ROWB + (lane >> 4) * 16;
    const uint32_t boff = (uint32_t)(wn + ((lane >> 4) & 1) * 8 + (lane & 7)) * ROWB
                        + ((lane >> 3) & 1) * 16;

    float acc[2][8][4];
#pragma unroll
    for (int mi = 0; mi < 2; mi++)
#pragma unroll
        for (int ni = 0; ni < 8; ni++)
#pragma unroll
            for (int q = 0; q < 4; q++) acc[mi][ni][q] = 0.f;

#define PREFETCH(CH, SBUF)                                                            \
    {                                                                                 \
        const size_t kb = (size_t)(CH) * TK;                                          \
        const uint32_t s0 = sb + (SBUF) * STAGE;                                      \
        const char* axh = (const char*)(g_xh + (size_t)(cm + lr) * HID + kb);         \
        const char* axl = (const char*)(g_xl + (size_t)(cm + lr) * HID + kb);         \
        uint32_t da = s0 + lr * ROWB;                                                 \
        cp16(da + lj, axh + lj);            cp16(da + lj + 64, axh + lj + 64);        \
        cp16(da + A_BYTES + lj, axl + lj);  cp16(da + A_BYTES + lj + 64, axl + lj + 64); \
        _Pragma("unroll")                                                             \
        for (int q = 0; q < 2; q++) {                                                 \
            int n = lr + q * 128;                                                     \
            const char* bwh = (const char*)(g_wh + (size_t)(cn + n) * HID + kb);      \
            const char* bwl = (const char*)(g_wl + (size_t)(cn + n) * HID + kb);      \
            uint32_t db = s0 + 2 * A_BYTES + n * ROWB;                                \
            cp16(db + lj, bwh + lj);            cp16(db + lj + 64, bwh + lj + 64);    \
            cp16(db + B_BYTES + lj, bwl + lj);  cp16(db + B_BYTES + lj + 64, bwl + lj + 64); \
        }                                                                             \
    }

    PREFETCH(0, 0);
    asm volatile("cp.async.commit_group;");
    asm volatile("cp.async.wait_group 0;");
    __syncthreads();

    for (int c = 0; c < NK; c++) {
        const int s = c & 1;
        if (c + 1 < NK) PREFETCH(c + 1, s ^ 1);
        asm volatile("cp.async.commit_group;");

        const uint32_t s0 = sb + s * STAGE;
        const uint32_t Ah = s0 + aoff;
        const uint32_t Al = s0 + A_BYTES + aoff;
        const uint32_t Bh = s0 + 2 * A_BYTES + boff;
        const uint32_t Bl = s0 + 2 * A_BYTES + B_BYTES + boff;

#pragma unroll
        for (int kf = 0; kf < 4; kf++) {
            const uint32_t cb = kf * 32;
            uint32_t ah[2][4], al[2][4];
#pragma unroll
            for (int mi = 0; mi < 2; mi++) {
                ldsm4(ah[mi], Ah + mi * 16 * ROWB + cb);
                ldsm4(al[mi], Al + mi * 16 * ROWB + cb);
            }
#pragma unroll
            for (int np = 0; np < 4; np++) {
                uint32_t bh4[4], bl4[4];
                ldsm4(bh4, Bh + np * 16 * ROWB + cb);
                ldsm4(bl4, Bl + np * 16 * ROWB + cb);
#pragma unroll
                for (int mi = 0; mi < 2; mi++) {
                    mma_bf16(acc[mi][2 * np],     ah[mi], bh4);
                    mma_bf16(acc[mi][2 * np],     ah[mi], bl4);
                    mma_bf16(acc[mi][2 * np],     al[mi], bh4);
                    mma_bf16(acc[mi][2 * np + 1], ah[mi], bh4 + 2);
                    mma_bf16(acc[mi][2 * np + 1], ah[mi], bl4 + 2);
                    mma_bf16(acc[mi][2 * np + 1], al[mi], bh4 + 2);
                }
            }
        }

        asm volatile("cp.async.wait_group 0;");
        __syncthreads();
    }

    const int qr = lane >> 2;
    const int qc = (lane & 3) * 2;
#pragma unroll
    for (int mi = 0; mi < 2; mi++) {
        int row = cm + wm + mi * 16 + qr;
        float* d0 = g_y + (size_t)row * DIMN + cn + wn;
        float* d1 = g_y + (size_t)(row + 8) * DIMN + cn + wn;
#pragma unroll
        for (int ni = 0; ni < 8; ni++) {
            *(float2*)(d0 + ni * 8 + qc) = make_float2(acc[mi][ni][0], acc[mi][ni][1]);
            *(float2*)(d1 + ni * 8 + qc) = make_float2(acc[mi][ni][2], acc[mi][ni][3]);
        }
    }
#undef PREFETCH
}

// ----------------- rfft(4096) per row: radix-4 fused Stockham -----------------
// Fuses radix-2 stage pairs (s, s+1) exactly (same mul/add order; the only
// change is w_{q'm+512} = w_{q'm} * (-i), an exact swap/negate identity).
__global__ void __launch_bounds__(256) fft_rows(const float* __restrict__ src, int mode) {
    __shared__ float2 bufA[2048];
    __shared__ float2 bufB[2048];
    __shared__ float red[256];
    const int t = threadIdx.x;
    const int row = blockIdx.x;
    const float* sp = (mode == 0) ? (g_y + (size_t)row * HID) : (src + (size_t)row * HID);

    float ns = 0.f;
    for (int i = t; i < 1024; i += 256) {
        float4 v = *(const float4*)(sp + i * 4);
        ns += v.x * v.x + v.y * v.y + v.z * v.z + v.w * v.w;
        bufA[2 * i]     = make_float2(v.x, v.y);
        bufA[2 * i + 1] = make_float2(v.z, v.w);
    }
    red[t] = ns;
    __syncthreads();
    for (int s2 = 128; s2 > 0; s2 >>= 1) {
        if (t < s2) red[t] += red[t + s2];
        __syncthreads();
    }
    const float invn = 1.f / fmaxf(sqrtf(red[0]), 1e-12f);

    float2* X = bufA;
    float2* Y = bufB;
    // 5 fused radix-4 stages covering radix-2 stages 0..9 (m = 1,4,16,64,256)
#pragma unroll
    for (int s = 0; s < 10; s += 2) {
        const int m = 1 << s;
#pragma unroll
        for (int uu = 0; uu < 2; uu++) {
            const int u = t + uu * 256;
            float2 A = X[u], B = X[u + 1024], C = X[u + 512], D = X[u + 1536];
            const int i1 = u & ~(m - 1);          // q'm
            float2 w1 = g_tw[i1];
            float2 w2 = g_tw[2 * i1];
            float2 s0 = make_float2(A.x + B.x, A.y + B.y);
            float2 s1 = make_float2(C.x + D.x, C.y + D.y);
            float2 d0 = cmulc(make_float2(A.x - B.x, A.y - B.y), w1);
            float2 d1 = cmulc(make_float2(C.x - D.x, C.y - D.y), w1);
            float2 d1r = make_float2(d1.y, -d1.x);          // * (-i)
            const int base = 4 * i1 + (u & (m - 1));        // 4q'm + r
            Y[base]         = make_float2(s0.x + s1.x, s0.y + s1.y);
            Y[base + m]     = make_float2(d0.x + d1r.x, d0.y + d1r.y);
            Y[base + 2 * m] = cmulc(make_float2(s0.x - s1.x, s0.y - s1.y), w2);
            Y[base + 3 * m] = cmulc(make_float2(d0.x - d1r.x, d0.y - d1r.y), w2);
        }
        float2* tmp = X; X = Y; Y = tmp;
        __syncthreads();
    }
    // final radix-2 stage (s=10, m=1024, twiddle = 1)
    for (int i = t; i < 1024; i += 256) {
        float2 a = X[i], b = X[i + 1024];
        Y[i]        = make_float2(a.x + b.x, a.y + b.y);
        Y[i + 1024] = make_float2(a.x - b.x, a.y - b.y);
    }
    {
        float2* tmp = X; X = Y; Y = tmp;
    }
    __syncthreads();

    for (int k = t; k <= 2048; k += 256) {
        float2 Ck = X[k & 2047];
        float2 Cm = X[(2048 - k) & 2047];
        Cm.y = -Cm.y;
        float2 tw = g_twr[k];
        float dx = Ck.x - Cm.x, dy = Ck.y - Cm.y;
        float p = tw.x * dx - tw.y * dy;
        float q = tw.x * dy + tw.y * dx;
        float2 Xk = make_float2((0.5f * (Ck.x + Cm.x) + 0.5f * q) * invn,
                                (0.5f * (Ck.y + Cm.y) - 0.5f * p) * invn);
        size_t o = (size_t)row * FP + k;
        if (mode == 0) {
            float2 r = g_RF[k];
            g_GF[o] = make_float2(Xk.x * r.x + Xk.y * r.y,
                                  Xk.y * r.x - Xk.x * r.y);
        } else if (mode == 1) {
            g_EF[o] = Xk;
            float w = (k == 0 || k == 2048) ? 1.f : 2.f;
            g_Esw[o] = make_float2(w * Xk.x, w * Xk.y);
        } else {
            g_LF[o] = Xk;
        }
    }
}

// ----------------- RF = sum_k EF_k * LF_k -----------------
__global__ void rf_kernel() {
    int k = blockIdx.x * 256 + threadIdx.x;
    if (k > 2048) return;
    float2 acc = make_float2(0.f, 0.f);
#pragma unroll 8
    for (int j = 0; j < NEXP; j++) {
        float2 e = g_EF[(size_t)j * FP + k];
        float2 l = g_LF[(size_t)j * FP + k];
        acc.x += e.x * l.x - e.y * l.y;
        acc.y += e.x * l.y + e.y * l.x;
    }
    g_RF[k] = acc;
}

// ----------------- similarity + softmax (iter) / outputs (final) -----------------
__global__ void __launch_bounds__(256) scores_kernel(const float2* __restrict__ Bsrc,
                                                     int final_mode, float* out,
                                                     int woff, int ioff, int soff) {
    __shared__ float2 A_s[16][33];
    __shared__ float2 E_s[16][65];
    __shared__ float  S_s[32][65];
    __shared__ float  nrm[32];
    const int t = threadIdx.x;
    const int rb = blockIdx.x * 32;
    if (t < 32) nrm[t] = 0.f;

    const int e  = t & 63;
    const int rg = t >> 6;
    const int la_row = t >> 3, la_f = (t & 7) * 2;
    const int le_e = t >> 2,  le_f = (t & 3) * 4;
    float2 acc[8];
#pragma unroll
    for (int i = 0; i < 8; i++) acc[i] = make_float2(0.f, 0.f);
    float nloc = 0.f;
    __syncthreads();

    for (int kb = 0; kb < NB; kb += 16) {
        {
            int k = kb + la_f;
            float4 v = make_float4(0.f, 0.f, 0.f, 0.f);
            if (k <= 2048) v = *(const float4*)&Bsrc[(size_t)(rb + la_row) * FP + k];
            A_s[la_f][la_row]     = make_float2(v.x, v.y);
            A_s[la_f + 1][la_row] = make_float2(v.z, v.w);
            float w0 = (k == 0 || k == 2048) ? 1.f : 2.f;
            nloc += w0 * (v.x * v.x + v.y * v.y) + 2.f * (v.z * v.z + v.w * v.w);
        }
        {
            int k = kb + le_f;
            float4 v0 = make_float4(0.f, 0.f, 0.f, 0.f);
            float4 v1 = make_float4(0.f, 0.f, 0.f, 0.f);
            if (k <= 2048) {
                const float4* p = (const float4*)&g_Esw[(size_t)le_e * FP + k];
                v0 = p[0]; v1 = p[1];
            }
            E_s[le_f][le_e]     = make_float2(v0.x, v0.y);
            E_s[le_f + 1][le_e] = make_float2(v0.z, v0.w);
            E_s[le_f + 2][le_e] = make_float2(v1.x, v1.y);
            E_s[le_f + 3][le_e] = make_float2(v1.z, v1.w);
        }
        __syncthreads();
#pragma unroll
        for (int f = 0; f < 16; f++) {
            float2 ev = E_s[f][e];
#pragma unroll
            for (int i = 0; i < 8; i++) {
                float2 av = A_s[f][rg * 8 + i];
                acc[i].x += av.x * ev.x;
                acc[i].y += av.y * ev.y;
            }
        }
        __syncthreads();
    }
#pragma unroll
    for (int i = 0; i < 8; i++) S_s[rg * 8 + i][e] = acc[i].x + acc[i].y;
    atomicAdd(&nrm[la_row], nloc);
    __syncthreads();

    if (t < 32) {
        int row = rb + t;
        float inv = rsqrtf(4096.f * fmaxf(nrm[t], 1e-30f));
        float mx = -1e30f;
        for (int j = 0; j < 64; j++) {
            float c = S_s[t][j] * inv;
            S_s[t][j] = c;
            mx = fmaxf(mx, c);
        }
        if (!final_mode) {
            float sum = 0.f;
            for (int j = 0; j < 64; j++) sum += expf(10.f * (S_s[t][j] - mx));
            float isum = 1.f / sum;
            for (int j = 0; j < 64; j++)
                g_attn[row * 64 + j] = expf(10.f * (S_s[t][j] - mx)) * isum;
        } else {
            float s1 = -1e30f, s2 = -1e30f;
            int i1 = 0, i2 = 0;
            for (int j = 0; j < 64; j++) {
                float c = S_s[t][j];
                if (c > s1)      { s2 = s1; i2 = i1; s1 = c; i1 = j; }
                else if (c > s2) { s2 = c; i2 = j; }
            }
            float w1 = 1.f / (1.f + expf(s2 - s1));
            if (woff >= 0) { out[woff + row * 2] = w1; out[woff + row * 2 + 1] = 1.f - w1; }
            if (ioff >= 0) { out[ioff + row * 2] = (float)i1; out[ioff + row * 2 + 1] = (float)i2; }
        }
    }
    if (final_mode) {
        __syncthreads();
        for (int idx = t; idx < 32 * 64; idx += 256)
            out[soff + (rb + (idx >> 6)) * 64 + (idx & 63)] = S_s[idx >> 6][idx & 63];
    }
}

// ----------------- A_next = GF * conj(attn @ EF) -----------------
__global__ void __launch_bounds__(256) update_kernel() {
    __shared__ float attn_s[16][65];
    const int t = threadIdx.x;
    const int rb = blockIdx.y * 16;
    const int kb = blockIdx.x * 128;
    for (int idx = t; idx < 16 * 64; idx += 256)
        attn_s[idx >> 6][idx & 63] = g_attn[(rb + (idx >> 6)) * 64 + (idx & 63)];
    __syncthreads();

    const int r  = t >> 4;
    const int fo = (t & 15) * 2;
    float2 acc[8];
#pragma unroll
    for (int m = 0; m < 8; m++) acc[m] = make_float2(0.f, 0.f);
#pragma unroll 4
    for (int j = 0; j < 64; j++) {
        float a = attn_s[r][j];
        const float4* ep = (const float4*)&g_EF[(size_t)j * FP + kb + fo];
#pragma unroll
        for (int m = 0; m < 4; m++) {
            float4 e = ep[m * 16];
            acc[2 * m].x     += a * e.x; acc[2 * m].y     += a * e.y;
            acc[2 * m + 1].x += a * e.z; acc[2 * m + 1].y += a * e.w;
        }
    }
    const size_t base = (size_t)(rb + r) * FP + kb + fo;
#pragma unroll
    for (int m = 0; m < 4; m++) {
        const float4 g4 = *(const float4*)&g_GF[base + m * 32];
        float2 z0 = acc[2 * m], z1 = acc[2 * m + 1];
        float4 o;
        o.x = g4.x * z0.x + g4.y * z0.y;
        o.y = g4.y * z0.x - g4.x * z0.y;
        o.z = g4.z * z1.x + g4.w * z1.y;
        o.w = g4.w * z1.x - g4.z * z1.y;
        *(float4*)&g_B[base + m * 32] = o;
    }
}

// ----------------- launch -----------------
extern "C" void kernel_launch(void* const* d_in, const int* in_sizes, int n_in,
                              void* d_out, int out_size) {
    const float* x      = (const float*)d_in[0];
    const float* W      = (const float*)d_in[1];
    const float* labels = (const float*)d_in[2];
    const float* sigs   = (const float*)d_in[3];
    float* out = (float*)d_out;

    cudaFuncSetAttribute(tc_gemm, cudaFuncAttributeMaxDynamicSharedMemorySize, GEMM_SMEM);

    init_tables<<<9, 256>>>();

    __nv_bfloat16 *xh, *xl, *wh, *wl;
    float2 *gfp, *bp;
    cudaGetSymbolAddress((void**)&xh, g_xh);
    cudaGetSymbolAddress((void**)&xl, g_xl);
    cudaGetSymbolAddress((void**)&wh, g_wh);
    cudaGetSymbolAddress((void**)&wl, g_wl);
    cudaGetSymbolAddress((void**)&gfp, g_GF);
    cudaGetSymbolAddress((void**)&bp, g_B);
    convert_split<<<(NROWS * HID) / (256 * 8), 256>>>(x, xh, xl);
    convert_split<<<(DIMN * HID) / (256 * 8), 256>>>(W, wh, wl);

    tc_gemm<<<dim3(DIMN / TN, NROWS / TM), 512, GEMM_SMEM>>>();

    fft_rows<<<NEXP, 256>>>(sigs, 1);
    fft_rows<<<NEXP, 256>>>(labels, 2);
    rf_kernel<<<9, 256>>>();
    fft_rows<<<NROWS, 256>>>(x, 0);

    scores_kernel<<<NROWS / 32, 256>>>(gfp, 0, nullptr, -1, -1, -1);
    update_kernel<<<dim3(17, NROWS / 16), 256>>>();
    for (int it = 1; it < 3; it++) {
        scores_kernel<<<NROWS / 32, 256>>>(bp, 0, nullptr, -1, -1, -1);
        update_kernel<<<dim3(17, NROWS / 16), 256>>>();
    }

    int woff = -1, ioff = -1, soff = 0;
    if (out_size >= NROWS * 68) { woff = 0; ioff = NROWS * 2; soff = NROWS * 4; }
    scores_kernel<<<NROWS / 32, 256>>>(bp, 1, out, woff, ioff, soff);
}